// round 3
// baseline (speedup 1.0000x reference)
#include <cuda_runtime.h>
#include <cstdint>

// CIC deposition: 10M particles -> 256^3 float grid.
// Round 3: 4 particles/thread via float4 loads (1 LDG.128 per particle instead
// of 4 scalar LDGs), streaming loads (__ldcs) to protect L2-resident grid,
// keeping the predicated red.global.add.v4.f32 z-pair scheme from round 2.

static constexpr int   NC    = 256;
static constexpr float GMINF = -10.0f;
static constexpr float DXF   = (float)(20.0 / 255.0);

__global__ void zero_grid_kernel(float4* __restrict__ out, int n4) {
    int i = blockIdx.x * blockDim.x + threadIdx.x;
    if (i < n4) out[i] = make_float4(0.f, 0.f, 0.f, 0.f);
}

__device__ __forceinline__ void red_v4p(float* p, float a, float b, float c, float d, int pred) {
    asm volatile(
        "{\n\t"
        ".reg .pred q;\n\t"
        "setp.ne.s32 q, %5, 0;\n\t"
        "@q red.global.add.v4.f32 [%0], {%1, %2, %3, %4};\n\t"
        "}"
        :: "l"(p), "f"(a), "f"(b), "f"(c), "f"(d), "r"(pred) : "memory");
}

__device__ __forceinline__ void red_v1p(float* p, float a, int pred) {
    asm volatile(
        "{\n\t"
        ".reg .pred q;\n\t"
        "setp.ne.s32 q, %2, 0;\n\t"
        "@q red.global.add.f32 [%0], %1;\n\t"
        "}"
        :: "l"(p), "f"(a), "r"(pred) : "memory");
}

__device__ __forceinline__ void deposit_one(
    float px, float py, float pz, float w, float* __restrict__ grid)
{
    // Match JAX float32 arithmetic: subtract then IEEE divide
    float fx = (px - GMINF) / DXF;
    float fy = (py - GMINF) / DXF;
    float fz = (pz - GMINF) / DXF;

    float ix = floorf(fx), iy = floorf(fy), iz = floorf(fz);
    int cx = (int)ix, cy = (int)iy, cz = (int)iz;

    if ((unsigned)cx > 255u || (unsigned)cy > 255u || (unsigned)cz > 255u) return;

    float ox = fx - ix, oy = fy - iy, oz = fz - iz;

    float wx0 = w * (1.0f - ox);
    float wx1 = w * ox;
    float y0 = 1.0f - oy, y1 = oy;
    float z0 = 1.0f - oz, z1 = oz;

    bool bx = cx < (NC - 1);
    bool by = cy < (NC - 1);

    int  m    = cz & 3;
    int  use4 = (m != 3);
    int  fb   = !use4;
    int  fb2  = fb & (cz < (NC - 1));
    float a0 = (m == 0) ? 1.0f : 0.0f;
    float a1 = (m == 1) ? 1.0f : 0.0f;
    float a2 = (m == 2) ? 1.0f : 0.0f;

    float* g  = grid + (((size_t)cx * NC + (size_t)cy) * NC + (size_t)cz);
    float* gq = g - m;
    const size_t SX = (size_t)NC * NC;
    const size_t SY = NC;

    #define DEPOSIT_ROW(base_off, rw)  do {                                   \
        float v0 = (rw) * z0;                                                 \
        float v1 = (rw) * z1;                                                 \
        float l0 = v0 * a0;                                                   \
        float l1 = fmaf(v1, a0, v0 * a1);                                     \
        float l2 = fmaf(v1, a1, v0 * a2);                                     \
        float l3 = v1 * a2;                                                   \
        red_v4p(gq + (base_off), l0, l1, l2, l3, use4);                       \
        red_v1p(g + (base_off), v0, fb);                                      \
        red_v1p(g + (base_off) + 1, v1, fb2);                                 \
    } while (0)

    DEPOSIT_ROW(0, wx0 * y0);
    if (by) DEPOSIT_ROW(SY, wx0 * y1);
    if (bx) {
        DEPOSIT_ROW(SX, wx1 * y0);
        if (by) DEPOSIT_ROW(SX + SY, wx1 * y1);
    }
    #undef DEPOSIT_ROW
}

__global__ void __launch_bounds__(256) cic_deposit_kernel(
    const float* __restrict__ pos,
    const float* __restrict__ wgt,
    float* __restrict__ grid,
    int n)
{
    int t = blockIdx.x * blockDim.x + threadIdx.x;
    int base = 4 * t;
    if (base >= n) return;

    if (base + 3 < n) {
        // 4 particles: 3 float4 of positions (12 floats) + 1 float4 of weights
        const float4* p4 = (const float4*)pos + 3 * (size_t)t;
        float4 A = __ldcs(p4 + 0);
        float4 B = __ldcs(p4 + 1);
        float4 C = __ldcs(p4 + 2);
        float4 W = __ldcs((const float4*)wgt + t);

        deposit_one(A.x, A.y, A.z, W.x, grid);
        deposit_one(A.w, B.x, B.y, W.y, grid);
        deposit_one(B.z, B.w, C.x, W.z, grid);
        deposit_one(C.y, C.z, C.w, W.w, grid);
    } else {
        // scalar tail
        for (int i = base; i < n; i++) {
            float px = __ldcs(pos + 3 * (size_t)i + 0);
            float py = __ldcs(pos + 3 * (size_t)i + 1);
            float pz = __ldcs(pos + 3 * (size_t)i + 2);
            float w  = __ldcs(wgt + i);
            deposit_one(px, py, pz, w, grid);
        }
    }
}

extern "C" void kernel_launch(void* const* d_in, const int* in_sizes, int n_in,
                              void* d_out, int out_size) {
    const float* positions = (const float*)d_in[0];
    const float* weights   = (const float*)d_in[1];
    float* grid = (float*)d_out;

    int n_particles = in_sizes[1];  // weights element count = N

    int n4 = out_size / 4;
    zero_grid_kernel<<<(n4 + 255) / 256, 256>>>((float4*)grid, n4);

    int n_threads_total = (n_particles + 3) / 4;
    int threads = 256;
    int blocks = (n_threads_total + threads - 1) / threads;
    cic_deposit_kernel<<<blocks, threads>>>(positions, weights, grid, n_particles);
}